// round 6
// baseline (speedup 1.0000x reference)
#include <cuda_runtime.h>
#include <cuda_bf16.h>
#include <math.h>

typedef unsigned long long ull;

#define B_SZ 4
#define T_SZ 12800
#define M_ROWS (B_SZ*T_SZ)   // 51200

// ---------------- static device scratch (no allocation anywhere) ----------------
__device__ __align__(256) float g_aux[4*128*50];
__device__ __align__(256) float g_up1[4*80*216];
__device__ __align__(256) float g_up2[4*80*1728];
__device__ __align__(256) float g_up3[4*80*13824];
__device__ __align__(256) float g_in0[M_ROWS*128];
__device__ __align__(256) float g_iw[512*128];
__device__ __align__(256) float g_h[M_ROWS*512];
__device__ __align__(256) float g_xp[M_ROWS*1536];
__device__ __align__(256) float g_cat[M_ROWS*544];
__device__ __align__(256) float g_f1[M_ROWS*512];
__device__ __align__(256) float g_f2[M_ROWS*512];
__device__ __align__(256) float g_hst2[2][2048];   // [buf][hidx*4 + b]
__device__ __align__(256) unsigned g_flags[512];   // per-warp step flags

// ---------------- f32x2 / sync / math helpers ----------------
__device__ __forceinline__ ull pack2(float x, float y) {
    ull r; asm("mov.b64 %0, {%1,%2};" : "=l"(r) : "f"(x), "f"(y)); return r;
}
__device__ __forceinline__ ull dup2(float x) {
    ull r; unsigned u = __float_as_uint(x);
    asm("mov.b64 %0, {%1,%1};" : "=l"(r) : "r"(u)); return r;
}
__device__ __forceinline__ float2 unpack2(ull v) {
    float2 f; asm("mov.b64 {%0,%1}, %2;" : "=f"(f.x), "=f"(f.y) : "l"(v)); return f;
}
__device__ __forceinline__ void fma2(ull& d, ull a, ull b) {
    asm("fma.rn.f32x2 %0, %1, %2, %0;" : "+l"(d) : "l"(a), "l"(b));
}
__device__ __forceinline__ ull add2(ull a, ull b) {
    ull r; asm("add.rn.f32x2 %0, %1, %2;" : "=l"(r) : "l"(a), "l"(b)); return r;
}
__device__ __forceinline__ void st_rel_v4(float* p, float4 v) {
    asm volatile("st.release.gpu.global.v4.f32 [%0], {%1,%2,%3,%4};"
                 :: "l"(p), "f"(v.x), "f"(v.y), "f"(v.z), "f"(v.w) : "memory");
}
__device__ __forceinline__ void st_rel_u32(unsigned* p, unsigned v) {
    asm volatile("st.release.gpu.global.u32 [%0], %1;" :: "l"(p), "r"(v) : "memory");
}
__device__ __forceinline__ uint4 ld_acq_v4(const unsigned* p) {
    uint4 v;
    asm volatile("ld.acquire.gpu.global.v4.u32 {%0,%1,%2,%3}, [%4];"
                 : "=r"(v.x), "=r"(v.y), "=r"(v.z), "=r"(v.w) : "l"(p) : "memory");
    return v;
}
__device__ __forceinline__ float tanh_fast(float x) {
    float y; asm("tanh.approx.f32 %0, %1;" : "=f"(y) : "f"(x)); return y;
}
__device__ __forceinline__ float sig_fast(float x) {
    return fmaf(tanh_fast(0.5f * x), 0.5f, 0.5f);
}

// ---------------- reset (flags + GRU state) ----------------
__global__ void k_reset() {
    int i = blockIdx.x*blockDim.x + threadIdx.x;
    if (i < 512) g_flags[i] = 0u;
    int j = i - 512;
    if (j >= 0 && j < 4096) ((float*)g_hst2)[j] = 0.f;
}

// ---------------- mel resnet: one CTA per (b,l) column ----------------
__global__ void k_resnet(const float* __restrict__ mels, const float* __restrict__ w_in,
                         const float* __restrict__ bn0g, const float* __restrict__ bn0b,
                         const float* __restrict__ rc1, const float* __restrict__ rc2,
                         const float* __restrict__ rbn1g, const float* __restrict__ rbn1b,
                         const float* __restrict__ rbn2g, const float* __restrict__ rbn2b,
                         const float* __restrict__ cw, const float* __restrict__ cb,
                         float* __restrict__ aux) {
    int b = blockIdx.x / 50, l = blockIdx.x % 50;
    int o = threadIdx.x;
    __shared__ float mcol[400];
    __shared__ float xs[128], hs[128];
    const float sc = rsqrtf(1.0f + 1e-5f);

    for (int i = o; i < 400; i += 128) {
        int c = i / 5, k = i - c*5;
        mcol[i] = mels[(b*80 + c)*54 + l + k];
    }
    __syncthreads();

    float acc = 0.f;
    const float* wr = w_in + o*400;
    #pragma unroll 8
    for (int i = 0; i < 400; i++) acc += mcol[i] * __ldg(&wr[i]);
    acc = acc*(bn0g[o]*sc) + bn0b[o];
    xs[o] = fmaxf(acc, 0.f);

    for (int ib = 0; ib < 10; ib++) {
        __syncthreads();
        const float* r1 = rc1 + (ib*128 + o)*128;
        float h1 = 0.f;
        #pragma unroll 8
        for (int c = 0; c < 128; c++) h1 += xs[c] * __ldg(&r1[c]);
        h1 = h1*(rbn1g[ib*128+o]*sc) + rbn1b[ib*128+o];
        hs[o] = fmaxf(h1, 0.f);
        __syncthreads();
        const float* r2 = rc2 + (ib*128 + o)*128;
        float h2 = 0.f;
        #pragma unroll 8
        for (int c = 0; c < 128; c++) h2 += hs[c] * __ldg(&r2[c]);
        h2 = h2*(rbn2g[ib*128+o]*sc) + rbn2b[ib*128+o];
        float xn = h2 + xs[o];
        __syncthreads();
        xs[o] = xn;
    }
    __syncthreads();
    float a = 0.f;
    const float* cwr = cw + o*128;
    #pragma unroll 8
    for (int c = 0; c < 128; c++) a += xs[c] * __ldg(&cwr[c]);
    aux[(b*128 + o)*50 + l] = a + cb[o];
}

// ---------------- upsample stage ----------------
__global__ void k_upstage(const float* __restrict__ in, const float* __restrict__ w,
                          float* __restrict__ out, int L, int s, int K, int total) {
    int i = blockIdx.x*256 + threadIdx.x;
    if (i >= total) return;
    int Ls = L*s;
    int row = i / Ls, o = i - row*Ls;
    float acc = 0.f;
    for (int tap = 0; tap < K; tap++) {
        int p = o + tap - s;
        if (p >= 0 && p < Ls) acc += __ldg(&w[tap]) * __ldg(&in[row*L + p/s]);
    }
    out[i] = acc;
}

// ---------------- build padded input matrix for I-layer (M x 128) ----------------
__global__ void k_prep_in(const float* __restrict__ x, float* __restrict__ out) {
    int i = blockIdx.x*256 + threadIdx.x;
    if (i >= M_ROWS*128) return;
    int m = i >> 7, k = i & 127;
    int b = m / T_SZ, t = m - b*T_SZ;
    float v;
    if (k == 0)        v = x[m];
    else if (k <= 80)  v = g_up3[(b*80 + (k-1))*13824 + 512 + t];
    else if (k <= 112) v = g_aux[(b*128 + (k-81))*50 + t/256];
    else               v = 0.f;
    out[i] = v;
}

__global__ void k_pad_iw(const float* __restrict__ iw, float* __restrict__ o) {
    int i = blockIdx.x*256 + threadIdx.x;
    if (i >= 512*128) return;
    int n = i >> 7, k = i & 127;
    o[i] = (k < 113) ? iw[n*113 + k] : 0.f;
}

// ---------------- concat [h(512) | aux slice(32)] -> (M x 544) ----------------
__global__ void k_cat(const float* __restrict__ h, int aoff, float* __restrict__ out) {
    int i = blockIdx.x*256 + threadIdx.x;
    if (i >= M_ROWS*544) return;
    int m = i / 544, j = i - m*544;
    int b = m / T_SZ, t = m - b*T_SZ;
    out[i] = (j < 512) ? h[m*512 + j]
                       : g_aux[(b*128 + aoff + (j-512))*50 + t/256];
}

// ---------------- GEMM: C[m][n] = A[m,:K] . B[n,:K] + bias[n], optional relu ------
__global__ void __launch_bounds__(256) k_gemm(
        const float* __restrict__ A, const float* __restrict__ B,
        const float* __restrict__ bias, float* __restrict__ C,
        int N, int K, int relu) {
    __shared__ float As[16][132];
    __shared__ float Bs[16][132];
    int tid = threadIdx.x;
    int m0 = blockIdx.y*128, n0 = blockIdx.x*128;
    int tx = tid & 15, ty = tid >> 4;

    ull acc[8][4];
    #pragma unroll
    for (int i = 0; i < 8; i++)
        #pragma unroll
        for (int j = 0; j < 4; j++) acc[i][j] = 0ull;

    for (int kb = 0; kb < K; kb += 16) {
        #pragma unroll
        for (int i = tid; i < 512; i += 256) {
            int row = i >> 2, kq = (i & 3) * 4;
            float4 va = *(const float4*)&A[(size_t)(m0+row)*K + kb + kq];
            As[kq+0][row] = va.x; As[kq+1][row] = va.y;
            As[kq+2][row] = va.z; As[kq+3][row] = va.w;
            float4 vb = *(const float4*)&B[(size_t)(n0+row)*K + kb + kq];
            Bs[kq+0][row] = vb.x; Bs[kq+1][row] = vb.y;
            Bs[kq+2][row] = vb.z; Bs[kq+3][row] = vb.w;
        }
        __syncthreads();
        #pragma unroll
        for (int kk = 0; kk < 16; kk++) {
            float a[8];
            *(float4*)&a[0] = *(const float4*)&As[kk][ty*8];
            *(float4*)&a[4] = *(const float4*)&As[kk][ty*8+4];
            const ull* bp = (const ull*)&Bs[kk][tx*8];
            ull b2[4];
            #pragma unroll
            for (int j = 0; j < 4; j++) b2[j] = bp[j];
            #pragma unroll
            for (int i = 0; i < 8; i++) {
                ull ad = pack2(a[i], a[i]);
                #pragma unroll
                for (int j = 0; j < 4; j++) fma2(acc[i][j], ad, b2[j]);
            }
        }
        __syncthreads();
    }

    #pragma unroll
    for (int i = 0; i < 8; i++) {
        int m = m0 + ty*8 + i;
        float* cp = &C[(size_t)m*N + n0 + tx*8];
        #pragma unroll
        for (int j = 0; j < 4; j++) {
            float2 v = unpack2(acc[i][j]);
            float2 bb = *(const float2*)&bias[n0 + tx*8 + 2*j];
            v.x += bb.x; v.y += bb.y;
            if (relu) { v.x = fmaxf(v.x, 0.f); v.y = fmaxf(v.y, 0.f); }
            *(float2*)&cp[2*j] = v;
        }
    }
}

// ---------------- persistent GRU: 512 warps, 1 h-index per warp, flag barrier ----
// h layout [hidx*4+b]; producer publishes one float4 + flag with st.release;
// consumers poll all 512 flags (acquire) then __ldcg the 8KB h vector.
// No atomics, no __syncthreads: every warp fully self-paced.
__global__ void __launch_bounds__(128,1) k_gru(
        const float* __restrict__ whh, const float* __restrict__ bhh,
        const float* __restrict__ xp, float* __restrict__ hio) {
    const int lane = threadIdx.x & 31;
    const int hidx = blockIdx.x*4 + (threadIdx.x >> 5);

    // scalar weights: w[g][j128*4+q] for global j = lane*4+q + j128*128
    float w[3][16];
    #pragma unroll
    for (int g = 0; g < 3; g++) {
        const float* wg = whh + (size_t)(g*512 + hidx)*512;
        #pragma unroll
        for (int j128 = 0; j128 < 4; j128++)
            #pragma unroll
            for (int q = 0; q < 4; q++)
                w[g][j128*4+q] = __ldg(&wg[lane*4 + q + j128*128]);
    }
    const float b_r = __ldg(&bhh[hidx]);
    const float b_z = __ldg(&bhh[512+hidx]);
    const float b_n = __ldg(&bhh[1024+hidx]);

    // lane-0 state: per-batch gate inputs, residual, hidden state
    float hprev[4] = {0.f, 0.f, 0.f, 0.f};
    float xg[12], hres[4];
    if (lane == 0) {
        #pragma unroll
        for (int b = 0; b < 4; b++) {
            #pragma unroll
            for (int g = 0; g < 3; g++)
                xg[g*4+b] = __ldg(&xp[(b*T_SZ + 0)*1536 + g*512 + hidx]);
            hres[b] = __ldg(&hio[(b*T_SZ + 0)*512 + hidx]);
        }
    }

    for (int t = 0; t < T_SZ; t++) {
        const float* hin = g_hst2[t & 1];

        ull acc[3][2];   // [gate][(b0,b1)|(b2,b3)]
        #pragma unroll
        for (int g = 0; g < 3; g++) { acc[g][0] = 0ull; acc[g][1] = 0ull; }

        #pragma unroll
        for (int j128 = 0; j128 < 4; j128++) {
            float4 hv[4];
            #pragma unroll
            for (int q = 0; q < 4; q++)
                hv[q] = __ldcg((const float4*)(hin + (lane*4 + q + j128*128)*4));
            #pragma unroll
            for (int q = 0; q < 4; q++) {
                ull h01 = pack2(hv[q].x, hv[q].y);
                ull h23 = pack2(hv[q].z, hv[q].w);
                #pragma unroll
                for (int g = 0; g < 3; g++) {
                    ull wd = dup2(w[g][j128*4+q]);
                    fma2(acc[g][0], wd, h01);
                    fma2(acc[g][1], wd, h23);
                }
            }
        }

        // warp-reduce 6 packed pairs
        #pragma unroll
        for (int g = 0; g < 3; g++)
            #pragma unroll
            for (int p = 0; p < 2; p++)
                #pragma unroll
                for (int off = 16; off > 0; off >>= 1)
                    acc[g][p] = add2(acc[g][p],
                                     __shfl_xor_sync(0xffffffffu, acc[g][p], off));

        if (lane == 0) {
            float2 r01 = unpack2(acc[0][0]), r23 = unpack2(acc[0][1]);
            float2 z01 = unpack2(acc[1][0]), z23 = unpack2(acc[1][1]);
            float2 n01 = unpack2(acc[2][0]), n23 = unpack2(acc[2][1]);
            float pr[4] = {r01.x, r01.y, r23.x, r23.y};
            float pz[4] = {z01.x, z01.y, z23.x, z23.y};
            float pn[4] = {n01.x, n01.y, n23.x, n23.y};

            float hn[4];
            #pragma unroll
            for (int b = 0; b < 4; b++) {
                float r = sig_fast(xg[0+b] + pr[b] + b_r);
                float z = sig_fast(xg[4+b] + pz[b] + b_z);
                float n = tanh_fast(xg[8+b] + r * (pn[b] + b_n));
                hn[b] = (1.f - z)*n + z*hprev[b];
            }

            float4 hv4 = make_float4(hn[0], hn[1], hn[2], hn[3]);
            st_rel_v4((float*)(g_hst2[(t+1) & 1] + hidx*4), hv4);
            st_rel_u32(&g_flags[hidx], (unsigned)(t + 1));

            // off-critical-path: residual out + next-step prefetch
            #pragma unroll
            for (int b = 0; b < 4; b++)
                hio[(b*T_SZ + t)*512 + hidx] = hres[b] + hn[b];
            if (t + 1 < T_SZ) {
                #pragma unroll
                for (int b = 0; b < 4; b++) {
                    #pragma unroll
                    for (int g = 0; g < 3; g++)
                        xg[g*4+b] = __ldg(&xp[(b*T_SZ + t + 1)*1536 + g*512 + hidx]);
                    hres[b] = __ldg(&hio[(b*T_SZ + t + 1)*512 + hidx]);
                }
            }
            #pragma unroll
            for (int b = 0; b < 4; b++) hprev[b] = hn[b];
        }

        // poll all 512 per-warp flags: 16 per lane, one vote per iteration
        if (t + 1 < T_SZ) {
            const unsigned* fp = g_flags + lane*16;
            unsigned tgt = (unsigned)(t + 1);
            bool ok;
            do {
                uint4 f0 = ld_acq_v4(fp);
                uint4 f1 = ld_acq_v4(fp + 4);
                uint4 f2 = ld_acq_v4(fp + 8);
                uint4 f3 = ld_acq_v4(fp + 12);
                ok = f0.x >= tgt && f0.y >= tgt && f0.z >= tgt && f0.w >= tgt
                  && f1.x >= tgt && f1.y >= tgt && f1.z >= tgt && f1.w >= tgt
                  && f2.x >= tgt && f2.y >= tgt && f2.z >= tgt && f2.w >= tgt
                  && f3.x >= tgt && f3.y >= tgt && f3.z >= tgt && f3.w >= tgt;
            } while (!__all_sync(0xffffffffu, ok));
        }
    }
}

// ---------------- host ----------------
static float* sym_addr(const void* s) {
    void* p = nullptr;
    cudaGetSymbolAddress(&p, s);
    return (float*)p;
}

extern "C" void kernel_launch(void* const* d_in, const int* in_sizes, int n_in,
                              void* d_out, int out_size) {
    const float* x        = (const float*)d_in[0];
    const float* mels     = (const float*)d_in[1];
    const float* conv_in_w= (const float*)d_in[2];
    const float* bn0_g    = (const float*)d_in[3];
    const float* bn0_b    = (const float*)d_in[4];
    const float* res_c1   = (const float*)d_in[5];
    const float* res_c2   = (const float*)d_in[6];
    const float* rbn1_g   = (const float*)d_in[7];
    const float* rbn1_b   = (const float*)d_in[8];
    const float* rbn2_g   = (const float*)d_in[9];
    const float* rbn2_b   = (const float*)d_in[10];
    const float* conv_ow  = (const float*)d_in[11];
    const float* conv_ob  = (const float*)d_in[12];
    const float* up_w0    = (const float*)d_in[13];
    const float* up_w1    = (const float*)d_in[14];
    const float* up_w2    = (const float*)d_in[15];
    const float* I_w      = (const float*)d_in[16];
    const float* I_b      = (const float*)d_in[17];
    const float* r1_wih   = (const float*)d_in[18];
    const float* r1_whh   = (const float*)d_in[19];
    const float* r1_bih   = (const float*)d_in[20];
    const float* r1_bhh   = (const float*)d_in[21];
    const float* r2_wih   = (const float*)d_in[22];
    const float* r2_whh   = (const float*)d_in[23];
    const float* r2_bih   = (const float*)d_in[24];
    const float* r2_bhh   = (const float*)d_in[25];
    const float* fc1_w    = (const float*)d_in[26];
    const float* fc1_b    = (const float*)d_in[27];
    const float* fc2_w    = (const float*)d_in[28];
    const float* fc2_b    = (const float*)d_in[29];
    const float* fc3_w    = (const float*)d_in[30];
    const float* fc3_b    = (const float*)d_in[31];
    float* out = (float*)d_out;

    float* p_aux = sym_addr(g_aux);
    float* p_up1 = sym_addr(g_up1);
    float* p_up2 = sym_addr(g_up2);
    float* p_up3 = sym_addr(g_up3);
    float* p_in0 = sym_addr(g_in0);
    float* p_iw  = sym_addr(g_iw);
    float* p_h   = sym_addr(g_h);
    float* p_xp  = sym_addr(g_xp);
    float* p_cat = sym_addr(g_cat);
    float* p_f1  = sym_addr(g_f1);
    float* p_f2  = sym_addr(g_f2);

    // 1. aux (mel resnet) and upsample chain
    k_resnet<<<200, 128>>>(mels, conv_in_w, bn0_g, bn0_b, res_c1, res_c2,
                           rbn1_g, rbn1_b, rbn2_g, rbn2_b, conv_ow, conv_ob, p_aux);
    k_upstage<<<(4*80*216 + 255)/256, 256>>>(mels, up_w0, p_up1, 54, 4, 9, 4*80*216);
    k_upstage<<<(4*80*1728 + 255)/256, 256>>>(p_up1, up_w1, p_up2, 216, 8, 17, 4*80*1728);
    k_upstage<<<(4*80*13824 + 255)/256, 256>>>(p_up2, up_w2, p_up3, 1728, 8, 17, 4*80*13824);

    // 2. I layer: h0 = [x | m_up | a1] @ I_w.T + I_b
    k_pad_iw<<<(512*128 + 255)/256, 256>>>(I_w, p_iw);
    k_prep_in<<<(M_ROWS*128)/256, 256>>>(x, p_in0);
    k_gemm<<<dim3(4, 400), 256>>>(p_in0, p_iw, I_b, p_h, 512, 128, 0);

    // 3. GRU1: xp1 then persistent recurrence (h = ys + h)
    k_gemm<<<dim3(12, 400), 256>>>(p_h, r1_wih, r1_bih, p_xp, 1536, 512, 0);
    k_reset<<<18, 256>>>();
    k_gru<<<128, 128>>>(r1_whh, r1_bhh, p_xp, p_h);

    // 4. GRU2: cat(h, a2) -> xp2 -> recurrence
    k_cat<<<(M_ROWS*544 + 255)/256, 256>>>(p_h, 32, p_cat);
    k_gemm<<<dim3(12, 400), 256>>>(p_cat, r2_wih, r2_bih, p_xp, 1536, 544, 0);
    k_reset<<<18, 256>>>();
    k_gru<<<128, 128>>>(r2_whh, r2_bhh, p_xp, p_h);

    // 5. fc1 / fc2 / fc3
    k_cat<<<(M_ROWS*544 + 255)/256, 256>>>(p_h, 64, p_cat);
    k_gemm<<<dim3(4, 400), 256>>>(p_cat, fc1_w, fc1_b, p_f1, 512, 544, 1);
    k_cat<<<(M_ROWS*544 + 255)/256, 256>>>(p_f1, 96, p_cat);
    k_gemm<<<dim3(4, 400), 256>>>(p_cat, fc2_w, fc2_b, p_f2, 512, 544, 1);
    k_gemm<<<dim3(8, 400), 256>>>(p_f2, fc3_w, fc3_b, out, 1024, 512, 0);
}

// round 7
// speedup vs baseline: 3.3870x; 3.3870x over previous
#include <cuda_runtime.h>
#include <cuda_bf16.h>
#include <math.h>

typedef unsigned long long ull;

#define B_SZ 4
#define T_SZ 12800
#define M_ROWS (B_SZ*T_SZ)   // 51200

// ---------------- static device scratch (no allocation anywhere) ----------------
__device__ __align__(256) float g_aux[4*128*50];
__device__ __align__(256) float g_up1[4*80*216];
__device__ __align__(256) float g_up2[4*80*1728];
__device__ __align__(256) float g_up3[4*80*13824];
__device__ __align__(256) float g_in0[M_ROWS*128];
__device__ __align__(256) float g_iw[512*128];
__device__ __align__(256) float g_h[M_ROWS*512];
__device__ __align__(256) float g_xp[M_ROWS*1536];
__device__ __align__(256) float g_cat[M_ROWS*544];
__device__ __align__(256) float g_f1[M_ROWS*512];
__device__ __align__(256) float g_f2[M_ROWS*512];
__device__ __align__(256) float g_hst2[2][2048];   // [buf][hidx*4 + b]
__device__ unsigned g_arrive;

// ---------------- f32x2 / sync / math helpers ----------------
__device__ __forceinline__ ull pack2(float x, float y) {
    ull r; asm("mov.b64 %0, {%1,%2};" : "=l"(r) : "f"(x), "f"(y)); return r;
}
__device__ __forceinline__ ull dup2(float x) {
    ull r; unsigned u = __float_as_uint(x);
    asm("mov.b64 %0, {%1,%1};" : "=l"(r) : "r"(u)); return r;
}
__device__ __forceinline__ float2 unpack2(ull v) {
    float2 f; asm("mov.b64 {%0,%1}, %2;" : "=f"(f.x), "=f"(f.y) : "l"(v)); return f;
}
__device__ __forceinline__ void fma2(ull& d, ull a, ull b) {
    asm("fma.rn.f32x2 %0, %1, %2, %0;" : "+l"(d) : "l"(a), "l"(b));
}
__device__ __forceinline__ ull add2(ull a, ull b) {
    ull r; asm("add.rn.f32x2 %0, %1, %2;" : "=l"(r) : "l"(a), "l"(b)); return r;
}
__device__ __forceinline__ unsigned ld_acq(unsigned* p) {
    unsigned v; asm volatile("ld.acquire.gpu.u32 %0, [%1];" : "=r"(v) : "l"(p) : "memory"); return v;
}
__device__ __forceinline__ void red_rel_add(unsigned* p, unsigned v) {
    asm volatile("red.release.gpu.global.add.u32 [%0], %1;" :: "l"(p), "r"(v) : "memory");
}
__device__ __forceinline__ float tanh_fast(float x) {
    float y; asm("tanh.approx.f32 %0, %1;" : "=f"(y) : "f"(x)); return y;
}
__device__ __forceinline__ float sig_fast(float x) {
    return fmaf(tanh_fast(0.5f * x), 0.5f, 0.5f);
}

// ---------------- reset (counter + GRU state) ----------------
__global__ void k_reset() {
    int i = blockIdx.x*blockDim.x + threadIdx.x;
    if (i == 0) g_arrive = 0u;
    if (i < 4096) ((float*)g_hst2)[i] = 0.f;
}

// ---------------- mel resnet: one CTA per (b,l) column ----------------
__global__ void k_resnet(const float* __restrict__ mels, const float* __restrict__ w_in,
                         const float* __restrict__ bn0g, const float* __restrict__ bn0b,
                         const float* __restrict__ rc1, const float* __restrict__ rc2,
                         const float* __restrict__ rbn1g, const float* __restrict__ rbn1b,
                         const float* __restrict__ rbn2g, const float* __restrict__ rbn2b,
                         const float* __restrict__ cw, const float* __restrict__ cb,
                         float* __restrict__ aux) {
    int b = blockIdx.x / 50, l = blockIdx.x % 50;
    int o = threadIdx.x;
    __shared__ float mcol[400];
    __shared__ float xs[128], hs[128];
    const float sc = rsqrtf(1.0f + 1e-5f);

    for (int i = o; i < 400; i += 128) {
        int c = i / 5, k = i - c*5;
        mcol[i] = mels[(b*80 + c)*54 + l + k];
    }
    __syncthreads();

    float acc = 0.f;
    const float* wr = w_in + o*400;
    #pragma unroll 8
    for (int i = 0; i < 400; i++) acc += mcol[i] * __ldg(&wr[i]);
    acc = acc*(bn0g[o]*sc) + bn0b[o];
    xs[o] = fmaxf(acc, 0.f);

    for (int ib = 0; ib < 10; ib++) {
        __syncthreads();
        const float* r1 = rc1 + (ib*128 + o)*128;
        float h1 = 0.f;
        #pragma unroll 8
        for (int c = 0; c < 128; c++) h1 += xs[c] * __ldg(&r1[c]);
        h1 = h1*(rbn1g[ib*128+o]*sc) + rbn1b[ib*128+o];
        hs[o] = fmaxf(h1, 0.f);
        __syncthreads();
        const float* r2 = rc2 + (ib*128 + o)*128;
        float h2 = 0.f;
        #pragma unroll 8
        for (int c = 0; c < 128; c++) h2 += hs[c] * __ldg(&r2[c]);
        h2 = h2*(rbn2g[ib*128+o]*sc) + rbn2b[ib*128+o];
        float xn = h2 + xs[o];
        __syncthreads();
        xs[o] = xn;
    }
    __syncthreads();
    float a = 0.f;
    const float* cwr = cw + o*128;
    #pragma unroll 8
    for (int c = 0; c < 128; c++) a += xs[c] * __ldg(&cwr[c]);
    aux[(b*128 + o)*50 + l] = a + cb[o];
}

// ---------------- upsample stage ----------------
__global__ void k_upstage(const float* __restrict__ in, const float* __restrict__ w,
                          float* __restrict__ out, int L, int s, int K, int total) {
    int i = blockIdx.x*256 + threadIdx.x;
    if (i >= total) return;
    int Ls = L*s;
    int row = i / Ls, o = i - row*Ls;
    float acc = 0.f;
    for (int tap = 0; tap < K; tap++) {
        int p = o + tap - s;
        if (p >= 0 && p < Ls) acc += __ldg(&w[tap]) * __ldg(&in[row*L + p/s]);
    }
    out[i] = acc;
}

// ---------------- build padded input matrix for I-layer (M x 128) ----------------
__global__ void k_prep_in(const float* __restrict__ x, float* __restrict__ out) {
    int i = blockIdx.x*256 + threadIdx.x;
    if (i >= M_ROWS*128) return;
    int m = i >> 7, k = i & 127;
    int b = m / T_SZ, t = m - b*T_SZ;
    float v;
    if (k == 0)        v = x[m];
    else if (k <= 80)  v = g_up3[(b*80 + (k-1))*13824 + 512 + t];
    else if (k <= 112) v = g_aux[(b*128 + (k-81))*50 + t/256];
    else               v = 0.f;
    out[i] = v;
}

__global__ void k_pad_iw(const float* __restrict__ iw, float* __restrict__ o) {
    int i = blockIdx.x*256 + threadIdx.x;
    if (i >= 512*128) return;
    int n = i >> 7, k = i & 127;
    o[i] = (k < 113) ? iw[n*113 + k] : 0.f;
}

// ---------------- concat [h(512) | aux slice(32)] -> (M x 544) ----------------
__global__ void k_cat(const float* __restrict__ h, int aoff, float* __restrict__ out) {
    int i = blockIdx.x*256 + threadIdx.x;
    if (i >= M_ROWS*544) return;
    int m = i / 544, j = i - m*544;
    int b = m / T_SZ, t = m - b*T_SZ;
    out[i] = (j < 512) ? h[m*512 + j]
                       : g_aux[(b*128 + aoff + (j-512))*50 + t/256];
}

// ---------------- GEMM: C[m][n] = A[m,:K] . B[n,:K] + bias[n], optional relu ------
__global__ void __launch_bounds__(256) k_gemm(
        const float* __restrict__ A, const float* __restrict__ B,
        const float* __restrict__ bias, float* __restrict__ C,
        int N, int K, int relu) {
    __shared__ float As[16][132];
    __shared__ float Bs[16][132];
    int tid = threadIdx.x;
    int m0 = blockIdx.y*128, n0 = blockIdx.x*128;
    int tx = tid & 15, ty = tid >> 4;

    ull acc[8][4];
    #pragma unroll
    for (int i = 0; i < 8; i++)
        #pragma unroll
        for (int j = 0; j < 4; j++) acc[i][j] = 0ull;

    for (int kb = 0; kb < K; kb += 16) {
        #pragma unroll
        for (int i = tid; i < 512; i += 256) {
            int row = i >> 2, kq = (i & 3) * 4;
            float4 va = *(const float4*)&A[(size_t)(m0+row)*K + kb + kq];
            As[kq+0][row] = va.x; As[kq+1][row] = va.y;
            As[kq+2][row] = va.z; As[kq+3][row] = va.w;
            float4 vb = *(const float4*)&B[(size_t)(n0+row)*K + kb + kq];
            Bs[kq+0][row] = vb.x; Bs[kq+1][row] = vb.y;
            Bs[kq+2][row] = vb.z; Bs[kq+3][row] = vb.w;
        }
        __syncthreads();
        #pragma unroll
        for (int kk = 0; kk < 16; kk++) {
            float a[8];
            *(float4*)&a[0] = *(const float4*)&As[kk][ty*8];
            *(float4*)&a[4] = *(const float4*)&As[kk][ty*8+4];
            const ull* bp = (const ull*)&Bs[kk][tx*8];
            ull b2[4];
            #pragma unroll
            for (int j = 0; j < 4; j++) b2[j] = bp[j];
            #pragma unroll
            for (int i = 0; i < 8; i++) {
                ull ad = pack2(a[i], a[i]);
                #pragma unroll
                for (int j = 0; j < 4; j++) fma2(acc[i][j], ad, b2[j]);
            }
        }
        __syncthreads();
    }

    #pragma unroll
    for (int i = 0; i < 8; i++) {
        int m = m0 + ty*8 + i;
        float* cp = &C[(size_t)m*N + n0 + tx*8];
        #pragma unroll
        for (int j = 0; j < 4; j++) {
            float2 v = unpack2(acc[i][j]);
            float2 bb = *(const float2*)&bias[n0 + tx*8 + 2*j];
            v.x += bb.x; v.y += bb.y;
            if (relu) { v.x = fmaxf(v.x, 0.f); v.y = fmaxf(v.y, 0.f); }
            *(float2*)&cp[2*j] = v;
        }
    }
}

// ---------------- persistent GRU: 128 CTAs x 128 threads, 1 h-index per warp -----
// R5 counter barrier (proven) + SMEM staging of the 8KB h vector:
// each CTA __ldcg-stages h once per step (1MB/step grid-wide vs 4MB direct),
// all 4 warps compute from shared. h layout [hidx*4 + b].
__global__ void __launch_bounds__(128,1) k_gru(
        const float* __restrict__ whh, const float* __restrict__ bhh,
        const float* __restrict__ xp, float* __restrict__ hio) {
    const int lane = threadIdx.x & 31;
    const int hidx = blockIdx.x*4 + (threadIdx.x >> 5);
    const int tid = threadIdx.x;

    __shared__ __align__(16) float s_h[2048];

    // scalar weights: w[g][j128*4+q] for global j = lane*4+q + j128*128
    float w[3][16];
    #pragma unroll
    for (int g = 0; g < 3; g++) {
        const float* wg = whh + (size_t)(g*512 + hidx)*512;
        #pragma unroll
        for (int j128 = 0; j128 < 4; j128++)
            #pragma unroll
            for (int q = 0; q < 4; q++)
                w[g][j128*4+q] = __ldg(&wg[lane*4 + q + j128*128]);
    }
    const float b_r = __ldg(&bhh[hidx]);
    const float b_z = __ldg(&bhh[512+hidx]);
    const float b_n = __ldg(&bhh[1024+hidx]);

    // lane-0 state: per-batch gate inputs, residual, hidden state
    float hprev[4] = {0.f, 0.f, 0.f, 0.f};
    float xg[12], hres[4];
    if (lane == 0) {
        #pragma unroll
        for (int b = 0; b < 4; b++) {
            #pragma unroll
            for (int g = 0; g < 3; g++)
                xg[g*4+b] = __ldg(&xp[(b*T_SZ + 0)*1536 + g*512 + hidx]);
            hres[b] = __ldg(&hio[(b*T_SZ + 0)*512 + hidx]);
        }
    }

    for (int t = 0; t < T_SZ; t++) {
        // ---- stage h(t) into shared: 4 coalesced float4 per thread (L2, not L1) ----
        const float4* hin = (const float4*)g_hst2[t & 1];
        #pragma unroll
        for (int k = 0; k < 4; k++) {
            float4 v = __ldcg(hin + tid + k*128);
            *(float4*)&s_h[(tid + k*128)*4] = v;
        }
        __syncthreads();

        // ---- matvec from shared ----
        ull acc[3][2];   // [gate][(b0,b1)|(b2,b3)]
        #pragma unroll
        for (int g = 0; g < 3; g++) { acc[g][0] = 0ull; acc[g][1] = 0ull; }

        #pragma unroll
        for (int j128 = 0; j128 < 4; j128++) {
            #pragma unroll
            for (int q = 0; q < 4; q++) {
                int j = lane*4 + q + j128*128;
                float4 hv = *(const float4*)&s_h[j*4];
                ull h01 = pack2(hv.x, hv.y);
                ull h23 = pack2(hv.z, hv.w);
                #pragma unroll
                for (int g = 0; g < 3; g++) {
                    ull wd = dup2(w[g][j128*4+q]);
                    fma2(acc[g][0], wd, h01);
                    fma2(acc[g][1], wd, h23);
                }
            }
        }

        // warp-reduce 6 packed pairs
        #pragma unroll
        for (int g = 0; g < 3; g++)
            #pragma unroll
            for (int p = 0; p < 2; p++)
                #pragma unroll
                for (int off = 16; off > 0; off >>= 1)
                    acc[g][p] = add2(acc[g][p],
                                     __shfl_xor_sync(0xffffffffu, acc[g][p], off));

        float hn[4];
        if (lane == 0) {
            float2 r01 = unpack2(acc[0][0]), r23 = unpack2(acc[0][1]);
            float2 z01 = unpack2(acc[1][0]), z23 = unpack2(acc[1][1]);
            float2 n01 = unpack2(acc[2][0]), n23 = unpack2(acc[2][1]);
            float pr[4] = {r01.x, r01.y, r23.x, r23.y};
            float pz[4] = {z01.x, z01.y, z23.x, z23.y};
            float pn[4] = {n01.x, n01.y, n23.x, n23.y};

            #pragma unroll
            for (int b = 0; b < 4; b++) {
                float r = sig_fast(xg[0+b] + pr[b] + b_r);
                float z = sig_fast(xg[4+b] + pz[b] + b_z);
                float n = tanh_fast(xg[8+b] + r * (pn[b] + b_n));
                hn[b] = (1.f - z)*n + z*hprev[b];
                hprev[b] = hn[b];
            }
            *(float4*)&g_hst2[(t+1) & 1][hidx*4] =
                make_float4(hn[0], hn[1], hn[2], hn[3]);
        }

        __syncthreads();                     // all warps' h stores + smem reads done
        if (tid == 0) red_rel_add(&g_arrive, 1u);

        // off-critical-path: residual out + next-step prefetch (under barrier wait)
        if (lane == 0) {
            #pragma unroll
            for (int b = 0; b < 4; b++)
                hio[(b*T_SZ + t)*512 + hidx] = hres[b] + hn[b];
            if (t + 1 < T_SZ) {
                #pragma unroll
                for (int b = 0; b < 4; b++) {
                    #pragma unroll
                    for (int g = 0; g < 3; g++)
                        xg[g*4+b] = __ldg(&xp[(b*T_SZ + t + 1)*1536 + g*512 + hidx]);
                    hres[b] = __ldg(&hio[(b*T_SZ + t + 1)*512 + hidx]);
                }
            }
        }

        if (t + 1 < T_SZ) {
            if (tid == 0) {                  // single poller per CTA
                unsigned tgt = (unsigned)(t + 1) * 128u;
                while (ld_acq(&g_arrive) < tgt) {}
            }
            __syncthreads();                 // broadcast release to the CTA
        }
    }
}

// ---------------- host ----------------
static float* sym_addr(const void* s) {
    void* p = nullptr;
    cudaGetSymbolAddress(&p, s);
    return (float*)p;
}

extern "C" void kernel_launch(void* const* d_in, const int* in_sizes, int n_in,
                              void* d_out, int out_size) {
    const float* x        = (const float*)d_in[0];
    const float* mels     = (const float*)d_in[1];
    const float* conv_in_w= (const float*)d_in[2];
    const float* bn0_g    = (const float*)d_in[3];
    const float* bn0_b    = (const float*)d_in[4];
    const float* res_c1   = (const float*)d_in[5];
    const float* res_c2   = (const float*)d_in[6];
    const float* rbn1_g   = (const float*)d_in[7];
    const float* rbn1_b   = (const float*)d_in[8];
    const float* rbn2_g   = (const float*)d_in[9];
    const float* rbn2_b   = (const float*)d_in[10];
    const float* conv_ow  = (const float*)d_in[11];
    const float* conv_ob  = (const float*)d_in[12];
    const float* up_w0    = (const float*)d_in[13];
    const float* up_w1    = (const float*)d_in[14];
    const float* up_w2    = (const float*)d_in[15];
    const float* I_w      = (const float*)d_in[16];
    const float* I_b      = (const float*)d_in[17];
    const float* r1_wih   = (const float*)d_in[18];
    const float* r1_whh   = (const float*)d_in[19];
    const float* r1_bih   = (const float*)d_in[20];
    const float* r1_bhh   = (const float*)d_in[21];
    const float* r2_wih   = (const float*)d_in[22];
    const float* r2_whh   = (const float*)d_in[23];
    const float* r2_bih   = (const float*)d_in[24];
    const float* r2_bhh   = (const float*)d_in[25];
    const float* fc1_w    = (const float*)d_in[26];
    const float* fc1_b    = (const float*)d_in[27];
    const float* fc2_w    = (const float*)d_in[28];
    const float* fc2_b    = (const float*)d_in[29];
    const float* fc3_w    = (const float*)d_in[30];
    const float* fc3_b    = (const float*)d_in[31];
    float* out = (float*)d_out;

    float* p_aux = sym_addr(g_aux);
    float* p_up1 = sym_addr(g_up1);
    float* p_up2 = sym_addr(g_up2);
    float* p_up3 = sym_addr(g_up3);
    float* p_in0 = sym_addr(g_in0);
    float* p_iw  = sym_addr(g_iw);
    float* p_h   = sym_addr(g_h);
    float* p_xp  = sym_addr(g_xp);
    float* p_cat = sym_addr(g_cat);
    float* p_f1  = sym_addr(g_f1);
    float* p_f2  = sym_addr(g_f2);

    // 1. aux (mel resnet) and upsample chain
    k_resnet<<<200, 128>>>(mels, conv_in_w, bn0_g, bn0_b, res_c1, res_c2,
                           rbn1_g, rbn1_b, rbn2_g, rbn2_b, conv_ow, conv_ob, p_aux);
    k_upstage<<<(4*80*216 + 255)/256, 256>>>(mels, up_w0, p_up1, 54, 4, 9, 4*80*216);
    k_upstage<<<(4*80*1728 + 255)/256, 256>>>(p_up1, up_w1, p_up2, 216, 8, 17, 4*80*1728);
    k_upstage<<<(4*80*13824 + 255)/256, 256>>>(p_up2, up_w2, p_up3, 1728, 8, 17, 4*80*13824);

    // 2. I layer: h0 = [x | m_up | a1] @ I_w.T + I_b
    k_pad_iw<<<(512*128 + 255)/256, 256>>>(I_w, p_iw);
    k_prep_in<<<(M_ROWS*128)/256, 256>>>(x, p_in0);
    k_gemm<<<dim3(4, 400), 256>>>(p_in0, p_iw, I_b, p_h, 512, 128, 0);

    // 3. GRU1: xp1 then persistent recurrence (h = ys + h)
    k_gemm<<<dim3(12, 400), 256>>>(p_h, r1_wih, r1_bih, p_xp, 1536, 512, 0);
    k_reset<<<16, 256>>>();
    k_gru<<<128, 128>>>(r1_whh, r1_bhh, p_xp, p_h);

    // 4. GRU2: cat(h, a2) -> xp2 -> recurrence
    k_cat<<<(M_ROWS*544 + 255)/256, 256>>>(p_h, 32, p_cat);
    k_gemm<<<dim3(12, 400), 256>>>(p_cat, r2_wih, r2_bih, p_xp, 1536, 544, 0);
    k_reset<<<16, 256>>>();
    k_gru<<<128, 128>>>(r2_whh, r2_bhh, p_xp, p_h);

    // 5. fc1 / fc2 / fc3
    k_cat<<<(M_ROWS*544 + 255)/256, 256>>>(p_h, 64, p_cat);
    k_gemm<<<dim3(4, 400), 256>>>(p_cat, fc1_w, fc1_b, p_f1, 512, 544, 1);
    k_cat<<<(M_ROWS*544 + 255)/256, 256>>>(p_f1, 96, p_cat);
    k_gemm<<<dim3(4, 400), 256>>>(p_cat, fc2_w, fc2_b, p_f2, 512, 544, 1);
    k_gemm<<<dim3(8, 400), 256>>>(p_f2, fc3_w, fc3_b, out, 1024, 512, 0);
}